// round 14
// baseline (speedup 1.0000x reference)
#include <cuda_runtime.h>
#include <cstdint>

// GAGKNNQueryAndGroup on GB300.
// LAMBDA = 0.5 -> lam == 1-lam: rescale scales every distance by 0.5 uniformly,
// ordering is plain squared-distance KNN; components inputs dead.
//
// R14 = R13 with y-QUARTER chunks (64 pts) instead of halves (128 pts):
//  - ysort emits exact y bounds at sorted positions {0,63},{64,127},{128,191},
//    {192,255} of each 256-pt x-group -> 4 quarters with ~2x tighter y spans.
//  - knn scans 2 pts/lane (float2 loads, 2 ballots) per quarter; per-group
//    rb^2 + dy^2 skip test per quarter. Expected evaluated points ~halved.
//  - bootstrap: y-closest quarter, binary-search qy inside it, seed best with
//    the 32 contiguous y-nearest (masked out of the quarter's normal scan).
// Exactness: reference op order for distances (no FMA); top-32 of unique
// 64-bit (dist_bits<<32|idx) keys is processing-order invariant; ties by
// index == stable argsort. Exact quarter y-bounds used only for continue-
// skips (no monotonicity needed); group x bin-edge bounds monotone -> break
// safe; STOP margin 0.9999 >> fp rounding.

#define FULLMASK 0xffffffffu

constexpr int BATCH  = 4;
constexpr int NPTS   = 8192;
constexpr int NQUERY = 2048;
constexpr int NCH    = 64;
constexpr int NS     = 32;
constexpr int NBINS  = 256;
constexpr int NGR    = 32;                // 256-pt x-groups per batch
constexpr int NCHK   = 128;               // 64-pt y-quarter chunks per batch
constexpr int PARTS  = 8;
constexpr int PPTS   = NPTS / PARTS;      // 1024
constexpr int QPB    = 4;                 // queries (warps) per knn block
constexpr int KNN_THREADS = QPB * 32;     // 128
constexpr int BUFSZ  = 176;               // per-warp candidate buffer entries
constexpr float STOP = 0.9999f;

__device__ float g_bx[BATCH * NPTS];
__device__ float g_by[BATCH * NPTS];
__device__ float g_bz[BATCH * NPTS];
__device__ __align__(16) unsigned short g_bidx[BATCH * NPTS];
__device__ unsigned g_hist_part[BATCH * PARTS * NBINS];
__device__ unsigned g_partoff[BATCH * PARTS * NBINS];
__device__ int g_binstart[BATCH * NBINS];
__device__ float g_gxmin[BATCH * NGR];
__device__ float g_gxmax[BATCH * NGR];
__device__ float g_cymin[BATCH * NCHK];
__device__ float g_cymax[BATCH * NCHK];
__device__ int g_knn_idx[BATCH * NQUERY * NS];

__device__ __forceinline__ int binof(float x) {
    int b = (int)((x + 4.5f) * (NBINS / 9.0f));
    return min(max(b, 0), NBINS - 1);
}

// ---------------------------------------------------------------- prep ----
__global__ void hist_kernel(const float* __restrict__ xyz) {
    __shared__ unsigned h[NBINS];
    const int b = blockIdx.x / PARTS, p = blockIdx.x % PARTS;
    const int tid = threadIdx.x;
    for (int i = tid; i < NBINS; i += 256) h[i] = 0;
    __syncthreads();
    const int base = p * PPTS;
    for (int i = tid; i < PPTS; i += 256) {
        float x = xyz[((size_t)b * NPTS + base + i) * 3];
        atomicAdd(&h[binof(x)], 1u);
    }
    __syncthreads();
    for (int i = tid; i < NBINS; i += 256)
        g_hist_part[((size_t)b * PARTS + p) * NBINS + i] = h[i];
}

__global__ void scan_kernel() {
    __shared__ unsigned wsum[8];
    __shared__ int sstart[NBINS];
    const int b = blockIdx.x;
    const int tid = threadIdx.x;          // == bin, 256 threads
    const int lane = tid & 31, wid = tid >> 5;

    unsigned v = 0;
    #pragma unroll
    for (int p = 0; p < PARTS; p++)
        v += g_hist_part[((size_t)b * PARTS + p) * NBINS + tid];

    unsigned incl = v;
    #pragma unroll
    for (int off = 1; off < 32; off <<= 1) {
        unsigned t = __shfl_up_sync(FULLMASK, incl, off);
        if (lane >= off) incl += t;
    }
    if (lane == 31) wsum[wid] = incl;
    __syncthreads();
    if (wid == 0) {
        unsigned s = (lane < 8) ? wsum[lane] : 0, o = s;
        #pragma unroll
        for (int off = 1; off < 8; off <<= 1) {
            unsigned t = __shfl_up_sync(FULLMASK, s, off);
            if (lane >= off) s += t;
        }
        if (lane < 8) wsum[lane] = s - o;
    }
    __syncthreads();
    unsigned excl = incl - v + wsum[wid];
    sstart[tid] = (int)excl;
    g_binstart[b * NBINS + tid] = (int)excl;

    unsigned run = excl;
    #pragma unroll
    for (int p = 0; p < PARTS; p++) {
        g_partoff[((size_t)b * PARTS + p) * NBINS + tid] = run;
        run += g_hist_part[((size_t)b * PARTS + p) * NBINS + tid];
    }
    __syncthreads();

    if (tid < NGR) {                      // conservative, MONOTONE group x-bounds
        int posL = tid * 256, posR = posL + 255;
        int lo = 0, hi = NBINS - 1;
        while (lo < hi) { int m = (lo + hi + 1) >> 1;
                          if (sstart[m] <= posL) lo = m; else hi = m - 1; }
        int binL = lo;
        lo = binL; hi = NBINS - 1;
        while (lo < hi) { int m = (lo + hi + 1) >> 1;
                          if (sstart[m] <= posR) lo = m; else hi = m - 1; }
        int binR = lo;
        float eL = (binL == 0) ? -1e30f
                 : binL * (9.0f / NBINS) - 4.5f - 1e-3f;
        float eR = (binR == NBINS - 1) ? 1e30f
                 : (binR + 1) * (9.0f / NBINS) - 4.5f + 1e-3f;
        g_gxmin[b * NGR + tid] = eL;
        g_gxmax[b * NGR + tid] = eR;
    }
}

__global__ void scatter_kernel(const float* __restrict__ xyz) {
    __shared__ unsigned cur[NBINS];
    const int b = blockIdx.x / PARTS, p = blockIdx.x % PARTS;
    const int tid = threadIdx.x;
    for (int i = tid; i < NBINS; i += 256)
        cur[i] = g_partoff[((size_t)b * PARTS + p) * NBINS + i];
    __syncthreads();
    const int base = p * PPTS;
    for (int i = tid; i < PPTS; i += 256) {
        const float* pt = xyz + ((size_t)b * NPTS + base + i) * 3;
        float x = pt[0], y = pt[1], z = pt[2];
        int pos = (int)atomicAdd(&cur[binof(x)], 1u);
        size_t o = (size_t)b * NPTS + pos;
        g_bx[o] = x; g_by[o] = y; g_bz[o] = z;
        g_bidx[o] = (unsigned short)(base + i);
    }
}

// Sort each 256-pt x-group by y (hybrid bitonic); emit exact quarter y-bounds.
__global__ void ysort_kernel() {
    __shared__ float sx[256], sy[256], sz[256];
    __shared__ unsigned short si[256];
    __shared__ unsigned long long sk[256];
    const int b = blockIdx.x / NGR, g = blockIdx.x % NGR;
    const int tid = threadIdx.x;
    const size_t base = (size_t)b * NPTS + g * 256;

    float y = g_by[base + tid];
    sx[tid] = g_bx[base + tid];
    sy[tid] = y;
    sz[tid] = g_bz[base + tid];
    si[tid] = g_bidx[base + tid];
    unsigned e = __float_as_uint(y);
    e = (e & 0x80000000u) ? ~e : (e | 0x80000000u);   // order-preserving
    unsigned long long v = ((unsigned long long)e << 32) | (unsigned)tid;

    auto shfl_stage = [&](int k, int j) {
        unsigned long long o = __shfl_xor_sync(FULLMASK, v, j);
        bool keepMin = (((tid & k) == 0) == ((tid & j) == 0));
        bool less = v < o;                 // keys unique -> consistent
        v = (less == keepMin) ? v : o;
    };
    auto smem_stage = [&](int k, int j) {
        sk[tid] = v;
        __syncthreads();
        unsigned long long o = sk[tid ^ j];
        bool keepMin = (((tid & k) == 0) == ((tid & j) == 0));
        bool less = v < o;
        v = (less == keepMin) ? v : o;
        __syncthreads();
    };

    #pragma unroll
    for (int k = 2; k <= 32; k <<= 1)
        for (int j = k >> 1; j > 0; j >>= 1) shfl_stage(k, j);
    smem_stage(64, 32);
    #pragma unroll
    for (int j = 16; j > 0; j >>= 1) shfl_stage(64, j);
    smem_stage(128, 64); smem_stage(128, 32);
    #pragma unroll
    for (int j = 16; j > 0; j >>= 1) shfl_stage(128, j);
    smem_stage(256, 128); smem_stage(256, 64); smem_stage(256, 32);
    #pragma unroll
    for (int j = 16; j > 0; j >>= 1) shfl_stage(256, j);

    int src = (int)(v & 0xffu);
    float yv = sy[src];
    g_bx[base + tid] = sx[src];
    g_by[base + tid] = yv;
    g_bz[base + tid] = sz[src];
    g_bidx[base + tid] = si[src];
    // quarter bounds at sorted positions 0/63/64/127/128/191/192/255
    const int qbase = b * NCHK + 4 * g;
    if ((tid & 63) == 0)  g_cymin[qbase + (tid >> 6)] = yv;
    if ((tid & 63) == 63) g_cymax[qbase + (tid >> 6)] = yv;
}

// ------------------------------------------------------------ knn utils ----
__device__ __forceinline__ float sqdist(float qx, float qy, float qz,
                                        float x, float y, float z) {
    // No FMA contraction: matches reference (diff*diff then sum) bit-exactly.
    float dx = qx - x, dy = qy - y, dz = qz - z;
    return __fadd_rn(__fadd_rn(__fmul_rn(dx, dx), __fmul_rn(dy, dy)),
                     __fmul_rn(dz, dz));
}

__device__ __forceinline__ void warp_sort32(unsigned long long& v, int lane) {
    #pragma unroll
    for (int k = 2; k <= 32; k <<= 1) {
        #pragma unroll
        for (int j = k >> 1; j > 0; j >>= 1) {
            unsigned long long o = __shfl_xor_sync(FULLMASK, v, j);
            bool keepMin = (((lane & k) == 0) == ((lane & j) == 0));
            bool less = v < o;
            v = (less == keepMin) ? v : o;
        }
    }
}

__device__ __forceinline__ void warp_merge(unsigned long long& best,
                                           unsigned long long p, int lane) {
    unsigned long long bo = __shfl_sync(FULLMASK, p, 31 - lane);
    unsigned long long v = (best < bo) ? best : bo;
    #pragma unroll
    for (int j = 16; j > 0; j >>= 1) {
        unsigned long long o = __shfl_xor_sync(FULLMASK, v, j);
        bool lower = (lane & j) == 0;
        bool less = v < o;
        v = (less == lower) ? v : o;
    }
    best = v;
}

// ----------------------------------------------------------------- knn ----
__global__ __launch_bounds__(KNN_THREADS, 12)
void knn_kernel(const float* __restrict__ new_xyz) {
    __shared__ float sgxmin[NGR], sgxmax[NGR], scymin[NCHK], scymax[NCHK];
    __shared__ unsigned long long sbuf[QPB][BUFSZ];

    const int blocks_per_batch = NQUERY / QPB;   // 512
    const int b    = blockIdx.x / blocks_per_batch;
    const int qblk = blockIdx.x % blocks_per_batch;

    if (threadIdx.x < NCHK) {
        scymin[threadIdx.x] = g_cymin[b * NCHK + threadIdx.x];
        scymax[threadIdx.x] = g_cymax[b * NCHK + threadIdx.x];
        if (threadIdx.x < NGR) {
            sgxmin[threadIdx.x] = g_gxmin[b * NGR + threadIdx.x];
            sgxmax[threadIdx.x] = g_gxmax[b * NGR + threadIdx.x];
        }
    }
    __syncthreads();

    const int w    = threadIdx.x >> 5;
    const int lane = threadIdx.x & 31;
    const int q    = qblk * QPB + w;
    unsigned long long* buf = sbuf[w];

    const float* bxp = g_bx + (size_t)b * NPTS;
    const float* byp = g_by + (size_t)b * NPTS;
    const float* bzp = g_bz + (size_t)b * NPTS;
    const unsigned short* bip = g_bidx + (size_t)b * NPTS;
    const float2* px = (const float2*)bxp;
    const float2* py = (const float2*)byp;
    const float2* pz = (const float2*)bzp;
    const unsigned* pi = (const unsigned*)bip;

    const float* nq = new_xyz + ((size_t)b * NQUERY + q) * 3;
    const float qx = __ldg(nq), qy = __ldg(nq + 1), qz = __ldg(nq + 2);

    unsigned long long best = ~0ULL;
    unsigned thrBits = 0xffffffffu;
    int cnt = 0;
    const unsigned lmask = (1u << lane) - 1u;

    // distance from qy to quarter c's exact y-range (0 if inside)
    auto ydist = [&](int c) {
        return fmaxf(fmaxf(__fsub_rn(scymin[c], qy),
                           __fsub_rn(qy, scymax[c])), 0.0f);
    };

    // ---- scan one 64-pt quarter (2 pts/lane); mask [ms, ms+32) if ms>=0 ----
    auto scan_chunk = [&](int c, int ms) {
        const int e = c * 32 + lane;       // float2 element index
        float2 X = __ldg(px + e);
        float2 Y = __ldg(py + e);
        float2 Z = __ldg(pz + e);

        unsigned u0 = __float_as_uint(sqdist(qx, qy, qz, X.x, Y.x, Z.x));
        unsigned u1 = __float_as_uint(sqdist(qx, qy, qz, X.y, Y.y, Z.y));

        if (ms >= 0) {                    // bootstrap-duplicate mask
            const int i0 = c * 64 + lane * 2;
            if ((unsigned)(i0 + 0 - ms) < 32u) u0 = 0xffffffffu;
            if ((unsigned)(i0 + 1 - ms) < 32u) u1 = 0xffffffffu;
        }

        unsigned mn = min(u0, u1);
        if (!__ballot_sync(FULLMASK, mn <= thrBits)) return;

        unsigned pk = __ldg(pi + e);       // two u16 orig indices
        unsigned m0 = __ballot_sync(FULLMASK, u0 <= thrBits);
        if (m0) {
            if ((m0 >> lane) & 1u)
                buf[cnt + __popc(m0 & lmask)] =
                    ((unsigned long long)u0 << 32) | (pk & 0xffffu);
            cnt += __popc(m0);
        }
        unsigned m1 = __ballot_sync(FULLMASK, u1 <= thrBits);
        if (m1) {
            if ((m1 >> lane) & 1u)
                buf[cnt + __popc(m1 & lmask)] =
                    ((unsigned long long)u1 << 32) | (pk >> 16);
            cnt += __popc(m1);
        }

        while (cnt >= 32) {               // drain (LIFO)
            __syncwarp(FULLMASK);
            unsigned long long v = buf[cnt - 32 + lane];
            cnt -= 32;
            warp_sort32(v, lane);
            warp_merge(best, v, lane);
            thrBits = (unsigned)(__shfl_sync(FULLMASK, best, 31) >> 32);
        }
    };

    const int pos0 = __ldg(&g_binstart[b * NBINS + binof(qx)]);
    const int g0 = min(pos0 >> 8, NGR - 1);

    // pick bootstrap quarter = y-closest quarter of the query's own group
    int cb = 4 * g0;
    {
        float bd = ydist(cb);
        #pragma unroll
        for (int h = 1; h < 4; h++) {
            float d = ydist(4 * g0 + h);
            if (d < bd) { bd = d; cb = 4 * g0 + h; }
        }
    }

    {   // bootstrap: 32 contiguous y-nearest points of cb (y-sorted)
        int lo = cb * 64, hi = lo + 64;
        while (lo < hi) {
            int m = (lo + hi) >> 1;
            if (byp[m] < qy) lo = m + 1; else hi = m;
        }
        int start = min(max(lo - 16, cb * 64), cb * 64 + 32);
        int pt = start + lane;
        float X = __ldg(bxp + pt), Y = __ldg(byp + pt), Z = __ldg(bzp + pt);
        unsigned short id = __ldg(bip + pt);
        unsigned long long v =
            ((unsigned long long)__float_as_uint(sqdist(qx, qy, qz, X, Y, Z)) << 32)
            | (unsigned)id;
        warp_sort32(v, lane);
        best = v;                          // 32 sorted real keys
        thrBits = (unsigned)(__shfl_sync(FULLMASK, best, 31) >> 32);

        scan_chunk(cb, start);             // rest of own quarter, masked

        #pragma unroll
        for (int h = 0; h < 4; h++) {      // other quarters of own group
            int c = 4 * g0 + h;
            if (c == cb) continue;
            float dy = ydist(c);
            if (!(__fmul_rn(__fmul_rn(dy, dy), STOP) > __uint_as_float(thrBits)))
                scan_chunk(c, -1);
        }
    }

    // right phase (group x-bounds monotone -> break safe)
    for (int g = g0 + 1; g < NGR; g++) {
        float rb = fmaxf(__fsub_rn(sgxmin[g], qx), 0.0f);
        float rb2 = __fmul_rn(rb, rb);
        if (__fmul_rn(rb2, STOP) > __uint_as_float(thrBits)) break;
        #pragma unroll
        for (int h = 0; h < 4; h++) {
            int c = 4 * g + h;
            float dy = ydist(c);
            float bound = __fadd_rn(rb2, __fmul_rn(dy, dy));
            if (!(__fmul_rn(bound, STOP) > __uint_as_float(thrBits)))
                scan_chunk(c, -1);
        }
    }
    // left phase
    for (int g = g0 - 1; g >= 0; g--) {
        float lb = fmaxf(__fsub_rn(qx, sgxmax[g]), 0.0f);
        float lb2 = __fmul_rn(lb, lb);
        if (__fmul_rn(lb2, STOP) > __uint_as_float(thrBits)) break;
        #pragma unroll
        for (int h = 0; h < 4; h++) {
            int c = 4 * g + h;
            float dy = ydist(c);
            float bound = __fadd_rn(lb2, __fmul_rn(dy, dy));
            if (!(__fmul_rn(bound, STOP) > __uint_as_float(thrBits)))
                scan_chunk(c, -1);
        }
    }

    if (cnt > 0) {       // final flush
        __syncwarp(FULLMASK);
        unsigned long long v = (lane < cnt) ? buf[lane] : ~0ULL;
        warp_sort32(v, lane);
        warp_merge(best, v, lane);
    }

    g_knn_idx[((size_t)b * NQUERY + q) * NS + lane] =
        (int)(unsigned)(best & 0xffffffffu);
}

// -------------------------------------------------------------- gather ----
constexpr int OUT_CH = 3 + NCH;                // 67
constexpr int ELEMS  = NQUERY * NS;            // 65536 per (b, ch)
constexpr int NV     = ELEMS / 4;              // 16384 float4 per (b, ch)
constexpr int NGRP   = 17;
constexpr int GSPLIT = 2;
constexpr int GATHER_THREADS = 1024;
constexpr int GATHER_SMEM = (NPTS + NQUERY) * 16;   // 160 KB

__global__ __launch_bounds__(GATHER_THREADS, 1)
void gather_kernel(const float* __restrict__ xyz,
                   const float* __restrict__ new_xyz,
                   const float* __restrict__ feats,
                   float* __restrict__ out) {
    extern __shared__ float4 s4[];
    float4* srow = s4;            // [NPTS]
    float4* sq   = s4 + NPTS;     // [NQUERY] (group 0 only)

    const int half = blockIdx.x % GSPLIT;
    const int bg   = blockIdx.x / GSPLIT;
    const int b    = bg / NGRP;
    const int g    = bg % NGRP;
    const int tid  = threadIdx.x;

    if (g > 0) {
        const int f0 = 4 * (g - 1);
        const float* c0 = feats + ((size_t)b * NCH + f0) * NPTS;
        const float* c1 = c0 + NPTS;
        const float* c2 = c1 + NPTS;
        const float* c3 = c2 + NPTS;
        for (int i = tid; i < NPTS; i += GATHER_THREADS)
            srow[i] = make_float4(__ldg(c0 + i), __ldg(c1 + i),
                                  __ldg(c2 + i), __ldg(c3 + i));
    } else {
        const float* src = xyz + (size_t)b * NPTS * 3;
        for (int i = tid; i < NPTS; i += GATHER_THREADS)
            srow[i] = make_float4(src[3 * i], src[3 * i + 1], src[3 * i + 2], 0.0f);
        const float* qs = new_xyz + (size_t)b * NQUERY * 3;
        for (int i = tid; i < NQUERY; i += GATHER_THREADS)
            sq[i] = make_float4(qs[3 * i], qs[3 * i + 1], qs[3 * i + 2], 0.0f);
    }
    __syncthreads();

    const int4* idx4 = reinterpret_cast<const int4*>(g_knn_idx + (size_t)b * ELEMS);
    constexpr int NVH = NV / GSPLIT;            // 8192 per block
    const int e0 = half * NVH;

    if (g > 0) {
        const int ch0 = 3 + 4 * (g - 1);
        float4* o = reinterpret_cast<float4*>(out + ((size_t)b * OUT_CH + ch0) * ELEMS);
        #pragma unroll
        for (int it = 0; it < NVH / GATHER_THREADS; it++) {
            int e = e0 + it * GATHER_THREADS + tid;
            int4 n = idx4[e];
            float4 p0 = srow[n.x], p1 = srow[n.y], p2 = srow[n.z], p3 = srow[n.w];
            o[e]          = make_float4(p0.x, p1.x, p2.x, p3.x);
            o[e + NV]     = make_float4(p0.y, p1.y, p2.y, p3.y);
            o[e + 2 * NV] = make_float4(p0.z, p1.z, p2.z, p3.z);
            o[e + 3 * NV] = make_float4(p0.w, p1.w, p2.w, p3.w);
        }
    } else {
        float4* o = reinterpret_cast<float4*>(out + (size_t)b * OUT_CH * ELEMS);
        #pragma unroll
        for (int it = 0; it < NVH / GATHER_THREADS; it++) {
            int e = e0 + it * GATHER_THREADS + tid;
            int4 n = idx4[e];
            float4 p0 = srow[n.x], p1 = srow[n.y], p2 = srow[n.z], p3 = srow[n.w];
            float4 qv = sq[e >> 3];             // query = (4e)/32
            o[e]          = make_float4(__fsub_rn(p0.x, qv.x), __fsub_rn(p1.x, qv.x),
                                        __fsub_rn(p2.x, qv.x), __fsub_rn(p3.x, qv.x));
            o[e + NV]     = make_float4(__fsub_rn(p0.y, qv.y), __fsub_rn(p1.y, qv.y),
                                        __fsub_rn(p2.y, qv.y), __fsub_rn(p3.y, qv.y));
            o[e + 2 * NV] = make_float4(__fsub_rn(p0.z, qv.z), __fsub_rn(p1.z, qv.z),
                                        __fsub_rn(p2.z, qv.z), __fsub_rn(p3.z, qv.z));
        }
    }
}

// -------------------------------------------------------------- launch ----
extern "C" void kernel_launch(void* const* d_in, const int* in_sizes, int n_in,
                              void* d_out, int out_size) {
    const float* xyz      = (const float*)d_in[0];   // (4, 8192, 3) f32
    const float* new_xyz  = (const float*)d_in[1];   // (4, 2048, 3) f32
    // d_in[2], d_in[3]: components (int64) -- dead (LAMBDA = 0.5)
    const float* feats    = (const float*)d_in[4];   // (4, 64, 8192) f32
    float* out = (float*)d_out;                      // (4, 67, 2048, 32) f32

    cudaFuncSetAttribute(gather_kernel,
                         cudaFuncAttributeMaxDynamicSharedMemorySize, GATHER_SMEM);

    hist_kernel<<<BATCH * PARTS, 256>>>(xyz);
    scan_kernel<<<BATCH, 256>>>();
    scatter_kernel<<<BATCH * PARTS, 256>>>(xyz);
    ysort_kernel<<<BATCH * NGR, 256>>>();
    knn_kernel<<<BATCH * (NQUERY / QPB), KNN_THREADS>>>(new_xyz);
    gather_kernel<<<BATCH * NGRP * GSPLIT, GATHER_THREADS, GATHER_SMEM>>>(
        xyz, new_xyz, feats, out);
}

// round 15
// speedup vs baseline: 1.2166x; 1.2166x over previous
#include <cuda_runtime.h>
#include <cstdint>

// GAGKNNQueryAndGroup on GB300.
// LAMBDA = 0.5 -> lam == 1-lam: rescale scales every distance by 0.5 uniformly,
// ordering is plain squared-distance KNN; components inputs dead.
//
// R15 = R13 (best measured: 80.8us; half-chunk granularity is the calibrated
// sweet spot -- R14's quarter-chunks regressed on per-chunk fixed overhead)
// plus ONE surgical change: the bootstrap's 7-step serial binary search
// (7 dependent gmem loads, ~300-400 serialized cyc/query) is replaced by a
// warp-parallel probe: one coalesced LDG at 32 evenly spaced positions +
// ballot + popc. The +-3-position approximation is provably harmless: the
// seed only affects initial threshold quality, never the result (top-32 of
// unique 64-bit keys is processing-order invariant).
// Exactness: reference op order for distances (no FMA); ties by index ==
// stable argsort; prune margin 0.9999 >> fp rounding; bounds conservative
// (bin edges for x, exact sorted extremes for y).

#define FULLMASK 0xffffffffu

constexpr int BATCH  = 4;
constexpr int NPTS   = 8192;
constexpr int NQUERY = 2048;
constexpr int NCH    = 64;
constexpr int NS     = 32;
constexpr int NBINS  = 256;
constexpr int NGR    = 32;                // 256-pt x-groups per batch
constexpr int NCHK   = 64;                // 128-pt y-half chunks per batch
constexpr int PARTS  = 8;
constexpr int PPTS   = NPTS / PARTS;      // 1024
constexpr int QPB    = 4;                 // queries (warps) per knn block
constexpr int KNN_THREADS = QPB * 32;     // 128
constexpr int BUFSZ  = 176;               // per-warp candidate buffer entries
constexpr float STOP = 0.9999f;

__device__ float g_bx[BATCH * NPTS];
__device__ float g_by[BATCH * NPTS];
__device__ float g_bz[BATCH * NPTS];
__device__ __align__(16) unsigned short g_bidx[BATCH * NPTS];
__device__ unsigned g_hist_part[BATCH * PARTS * NBINS];
__device__ unsigned g_partoff[BATCH * PARTS * NBINS];
__device__ int g_binstart[BATCH * NBINS];
__device__ float g_gxmin[BATCH * NGR];
__device__ float g_gxmax[BATCH * NGR];
__device__ float g_cymin[BATCH * NCHK];
__device__ float g_cymax[BATCH * NCHK];
__device__ int g_knn_idx[BATCH * NQUERY * NS];

__device__ __forceinline__ int binof(float x) {
    int b = (int)((x + 4.5f) * (NBINS / 9.0f));
    return min(max(b, 0), NBINS - 1);
}

// ---------------------------------------------------------------- prep ----
__global__ void hist_kernel(const float* __restrict__ xyz) {
    __shared__ unsigned h[NBINS];
    const int b = blockIdx.x / PARTS, p = blockIdx.x % PARTS;
    const int tid = threadIdx.x;
    for (int i = tid; i < NBINS; i += 256) h[i] = 0;
    __syncthreads();
    const int base = p * PPTS;
    for (int i = tid; i < PPTS; i += 256) {
        float x = xyz[((size_t)b * NPTS + base + i) * 3];
        atomicAdd(&h[binof(x)], 1u);
    }
    __syncthreads();
    for (int i = tid; i < NBINS; i += 256)
        g_hist_part[((size_t)b * PARTS + p) * NBINS + i] = h[i];
}

__global__ void scan_kernel() {
    __shared__ unsigned wsum[8];
    __shared__ int sstart[NBINS];
    const int b = blockIdx.x;
    const int tid = threadIdx.x;          // == bin, 256 threads
    const int lane = tid & 31, wid = tid >> 5;

    unsigned v = 0;
    #pragma unroll
    for (int p = 0; p < PARTS; p++)
        v += g_hist_part[((size_t)b * PARTS + p) * NBINS + tid];

    unsigned incl = v;
    #pragma unroll
    for (int off = 1; off < 32; off <<= 1) {
        unsigned t = __shfl_up_sync(FULLMASK, incl, off);
        if (lane >= off) incl += t;
    }
    if (lane == 31) wsum[wid] = incl;
    __syncthreads();
    if (wid == 0) {
        unsigned s = (lane < 8) ? wsum[lane] : 0, o = s;
        #pragma unroll
        for (int off = 1; off < 8; off <<= 1) {
            unsigned t = __shfl_up_sync(FULLMASK, s, off);
            if (lane >= off) s += t;
        }
        if (lane < 8) wsum[lane] = s - o;
    }
    __syncthreads();
    unsigned excl = incl - v + wsum[wid];
    sstart[tid] = (int)excl;
    g_binstart[b * NBINS + tid] = (int)excl;

    unsigned run = excl;
    #pragma unroll
    for (int p = 0; p < PARTS; p++) {
        g_partoff[((size_t)b * PARTS + p) * NBINS + tid] = run;
        run += g_hist_part[((size_t)b * PARTS + p) * NBINS + tid];
    }
    __syncthreads();

    if (tid < NGR) {                      // conservative, MONOTONE group x-bounds
        int posL = tid * 256, posR = posL + 255;
        int lo = 0, hi = NBINS - 1;
        while (lo < hi) { int m = (lo + hi + 1) >> 1;
                          if (sstart[m] <= posL) lo = m; else hi = m - 1; }
        int binL = lo;
        lo = binL; hi = NBINS - 1;
        while (lo < hi) { int m = (lo + hi + 1) >> 1;
                          if (sstart[m] <= posR) lo = m; else hi = m - 1; }
        int binR = lo;
        float eL = (binL == 0) ? -1e30f
                 : binL * (9.0f / NBINS) - 4.5f - 1e-3f;
        float eR = (binR == NBINS - 1) ? 1e30f
                 : (binR + 1) * (9.0f / NBINS) - 4.5f + 1e-3f;
        g_gxmin[b * NGR + tid] = eL;
        g_gxmax[b * NGR + tid] = eR;
    }
}

__global__ void scatter_kernel(const float* __restrict__ xyz) {
    __shared__ unsigned cur[NBINS];
    const int b = blockIdx.x / PARTS, p = blockIdx.x % PARTS;
    const int tid = threadIdx.x;
    for (int i = tid; i < NBINS; i += 256)
        cur[i] = g_partoff[((size_t)b * PARTS + p) * NBINS + i];
    __syncthreads();
    const int base = p * PPTS;
    for (int i = tid; i < PPTS; i += 256) {
        const float* pt = xyz + ((size_t)b * NPTS + base + i) * 3;
        float x = pt[0], y = pt[1], z = pt[2];
        int pos = (int)atomicAdd(&cur[binof(x)], 1u);
        size_t o = (size_t)b * NPTS + pos;
        g_bx[o] = x; g_by[o] = y; g_bz[o] = z;
        g_bidx[o] = (unsigned short)(base + i);
    }
}

// Sort each 256-pt x-group by y (hybrid bitonic: j<32 via shfl, else smem);
// emit exact per-half y bounds.
__global__ void ysort_kernel() {
    __shared__ float sx[256], sy[256], sz[256];
    __shared__ unsigned short si[256];
    __shared__ unsigned long long sk[256];
    const int b = blockIdx.x / NGR, g = blockIdx.x % NGR;
    const int tid = threadIdx.x;
    const size_t base = (size_t)b * NPTS + g * 256;

    float y = g_by[base + tid];
    sx[tid] = g_bx[base + tid];
    sy[tid] = y;
    sz[tid] = g_bz[base + tid];
    si[tid] = g_bidx[base + tid];
    unsigned e = __float_as_uint(y);
    e = (e & 0x80000000u) ? ~e : (e | 0x80000000u);   // order-preserving
    unsigned long long v = ((unsigned long long)e << 32) | (unsigned)tid;

    auto shfl_stage = [&](int k, int j) {
        unsigned long long o = __shfl_xor_sync(FULLMASK, v, j);
        bool keepMin = (((tid & k) == 0) == ((tid & j) == 0));
        bool less = v < o;                 // keys unique -> consistent
        v = (less == keepMin) ? v : o;
    };
    auto smem_stage = [&](int k, int j) {
        sk[tid] = v;
        __syncthreads();
        unsigned long long o = sk[tid ^ j];
        bool keepMin = (((tid & k) == 0) == ((tid & j) == 0));
        bool less = v < o;
        v = (less == keepMin) ? v : o;
        __syncthreads();
    };

    #pragma unroll
    for (int k = 2; k <= 32; k <<= 1)
        for (int j = k >> 1; j > 0; j >>= 1) shfl_stage(k, j);
    smem_stage(64, 32);
    #pragma unroll
    for (int j = 16; j > 0; j >>= 1) shfl_stage(64, j);
    smem_stage(128, 64); smem_stage(128, 32);
    #pragma unroll
    for (int j = 16; j > 0; j >>= 1) shfl_stage(128, j);
    smem_stage(256, 128); smem_stage(256, 64); smem_stage(256, 32);
    #pragma unroll
    for (int j = 16; j > 0; j >>= 1) shfl_stage(256, j);

    int src = (int)(v & 0xffu);
    float yv = sy[src];
    g_bx[base + tid] = sx[src];
    g_by[base + tid] = yv;
    g_bz[base + tid] = sz[src];
    g_bidx[base + tid] = si[src];
    if (tid == 0)   g_cymin[b * NCHK + 2 * g]     = yv;
    if (tid == 127) g_cymax[b * NCHK + 2 * g]     = yv;
    if (tid == 128) g_cymin[b * NCHK + 2 * g + 1] = yv;
    if (tid == 255) g_cymax[b * NCHK + 2 * g + 1] = yv;
}

// ------------------------------------------------------------ knn utils ----
__device__ __forceinline__ float sqdist(float qx, float qy, float qz,
                                        float x, float y, float z) {
    // No FMA contraction: matches reference (diff*diff then sum) bit-exactly.
    float dx = qx - x, dy = qy - y, dz = qz - z;
    return __fadd_rn(__fadd_rn(__fmul_rn(dx, dx), __fmul_rn(dy, dy)),
                     __fmul_rn(dz, dz));
}

__device__ __forceinline__ void warp_sort32(unsigned long long& v, int lane) {
    #pragma unroll
    for (int k = 2; k <= 32; k <<= 1) {
        #pragma unroll
        for (int j = k >> 1; j > 0; j >>= 1) {
            unsigned long long o = __shfl_xor_sync(FULLMASK, v, j);
            bool keepMin = (((lane & k) == 0) == ((lane & j) == 0));
            bool less = v < o;
            v = (less == keepMin) ? v : o;
        }
    }
}

__device__ __forceinline__ void warp_merge(unsigned long long& best,
                                           unsigned long long p, int lane) {
    unsigned long long bo = __shfl_sync(FULLMASK, p, 31 - lane);
    unsigned long long v = (best < bo) ? best : bo;
    #pragma unroll
    for (int j = 16; j > 0; j >>= 1) {
        unsigned long long o = __shfl_xor_sync(FULLMASK, v, j);
        bool lower = (lane & j) == 0;
        bool less = v < o;
        v = (less == lower) ? v : o;
    }
    best = v;
}

// ----------------------------------------------------------------- knn ----
__global__ __launch_bounds__(KNN_THREADS, 12)
void knn_kernel(const float* __restrict__ new_xyz) {
    __shared__ float sgxmin[NGR], sgxmax[NGR], scymin[NCHK], scymax[NCHK];
    __shared__ unsigned long long sbuf[QPB][BUFSZ];

    const int blocks_per_batch = NQUERY / QPB;   // 512
    const int b    = blockIdx.x / blocks_per_batch;
    const int qblk = blockIdx.x % blocks_per_batch;

    if (threadIdx.x < NCHK) {
        scymin[threadIdx.x] = g_cymin[b * NCHK + threadIdx.x];
        scymax[threadIdx.x] = g_cymax[b * NCHK + threadIdx.x];
        if (threadIdx.x < NGR) {
            sgxmin[threadIdx.x] = g_gxmin[b * NGR + threadIdx.x];
            sgxmax[threadIdx.x] = g_gxmax[b * NGR + threadIdx.x];
        }
    }
    __syncthreads();

    const int w    = threadIdx.x >> 5;
    const int lane = threadIdx.x & 31;
    const int q    = qblk * QPB + w;
    unsigned long long* buf = sbuf[w];

    const float* bxp = g_bx + (size_t)b * NPTS;
    const float* byp = g_by + (size_t)b * NPTS;
    const float* bzp = g_bz + (size_t)b * NPTS;
    const unsigned short* bip = g_bidx + (size_t)b * NPTS;
    const float4* px = (const float4*)bxp;
    const float4* py = (const float4*)byp;
    const float4* pz = (const float4*)bzp;
    const uint2*  pi = (const uint2*)bip;

    const float* nq = new_xyz + ((size_t)b * NQUERY + q) * 3;
    const float qx = __ldg(nq), qy = __ldg(nq + 1), qz = __ldg(nq + 2);

    unsigned long long best = ~0ULL;
    unsigned thrBits = 0xffffffffu;
    int cnt = 0;
    const unsigned lmask = (1u << lane) - 1u;

    // ---- append one chunk's candidates (optionally masking [ms, ms+32)) ----
    auto scan_chunk = [&](int c, int ms) {
        const int e0 = c * 32 + lane;
        float4 X = __ldg(px + e0);
        float4 Y = __ldg(py + e0);
        float4 Z = __ldg(pz + e0);

        unsigned u0 = __float_as_uint(sqdist(qx, qy, qz, X.x, Y.x, Z.x));
        unsigned u1 = __float_as_uint(sqdist(qx, qy, qz, X.y, Y.y, Z.y));
        unsigned u2 = __float_as_uint(sqdist(qx, qy, qz, X.z, Y.z, Z.z));
        unsigned u3 = __float_as_uint(sqdist(qx, qy, qz, X.w, Y.w, Z.w));

        if (ms >= 0) {                    // bootstrap-duplicate mask
            const int i0 = c * 128 + lane * 4;
            if ((unsigned)(i0 + 0 - ms) < 32u) u0 = 0xffffffffu;
            if ((unsigned)(i0 + 1 - ms) < 32u) u1 = 0xffffffffu;
            if ((unsigned)(i0 + 2 - ms) < 32u) u2 = 0xffffffffu;
            if ((unsigned)(i0 + 3 - ms) < 32u) u3 = 0xffffffffu;
        }

        unsigned mn = min(min(u0, u1), min(u2, u3));
        if (!__ballot_sync(FULLMASK, mn <= thrBits)) return;

        uint2 pk = __ldg(pi + e0);
        unsigned m0 = __ballot_sync(FULLMASK, u0 <= thrBits);
        if (m0) {
            if ((m0 >> lane) & 1u)
                buf[cnt + __popc(m0 & lmask)] =
                    ((unsigned long long)u0 << 32) | (pk.x & 0xffffu);
            cnt += __popc(m0);
        }
        unsigned m1 = __ballot_sync(FULLMASK, u1 <= thrBits);
        if (m1) {
            if ((m1 >> lane) & 1u)
                buf[cnt + __popc(m1 & lmask)] =
                    ((unsigned long long)u1 << 32) | (pk.x >> 16);
            cnt += __popc(m1);
        }
        unsigned m2 = __ballot_sync(FULLMASK, u2 <= thrBits);
        if (m2) {
            if ((m2 >> lane) & 1u)
                buf[cnt + __popc(m2 & lmask)] =
                    ((unsigned long long)u2 << 32) | (pk.y & 0xffffu);
            cnt += __popc(m2);
        }
        unsigned m3 = __ballot_sync(FULLMASK, u3 <= thrBits);
        if (m3) {
            if ((m3 >> lane) & 1u)
                buf[cnt + __popc(m3 & lmask)] =
                    ((unsigned long long)u3 << 32) | (pk.y >> 16);
            cnt += __popc(m3);
        }

        while (cnt >= 32) {               // drain (LIFO)
            __syncwarp(FULLMASK);
            unsigned long long v = buf[cnt - 32 + lane];
            cnt -= 32;
            warp_sort32(v, lane);
            warp_merge(best, v, lane);
            thrBits = (unsigned)(__shfl_sync(FULLMASK, best, 31) >> 32);
        }
    };

    const int pos0 = __ldg(&g_binstart[b * NBINS + binof(qx)]);
    const int g0 = min(pos0 >> 8, NGR - 1);

    // pick bootstrap half = the y-closer half of the query's own group
    const int ca = 2 * g0, cbh = 2 * g0 + 1;
    float dya = fmaxf(fmaxf(__fsub_rn(scymin[ca], qy),
                            __fsub_rn(qy, scymax[ca])), 0.0f);
    float dyb = fmaxf(fmaxf(__fsub_rn(scymin[cbh], qy),
                            __fsub_rn(qy, scymax[cbh])), 0.0f);
    const int cb = (dya <= dyb) ? ca : cbh;      // bootstrap half
    const int co = (dya <= dyb) ? cbh : ca;      // other half

    {   // bootstrap: ~32 contiguous y-near points of cb (y-sorted).
        // Warp-parallel probe replaces the 7-step serial binary search: one
        // coalesced LDG at stride-4 positions + ballot. +-3-position slack is
        // harmless (seed choice only affects initial thr, never the result).
        float yp = __ldg(byp + cb * 128 + lane * 4);
        unsigned below = __ballot_sync(FULLMASK, yp < qy);
        int lo = cb * 128 + __popc(below) * 4;   // ~first pos with y >= qy
        int start = min(max(lo - 16, cb * 128), cb * 128 + 96);
        int pt = start + lane;
        float X = __ldg(bxp + pt), Y = __ldg(byp + pt), Z = __ldg(bzp + pt);
        unsigned short id = __ldg(bip + pt);
        unsigned long long v =
            ((unsigned long long)__float_as_uint(sqdist(qx, qy, qz, X, Y, Z)) << 32)
            | (unsigned)id;
        warp_sort32(v, lane);
        best = v;                          // 32 sorted real keys
        thrBits = (unsigned)(__shfl_sync(FULLMASK, best, 31) >> 32);

        scan_chunk(cb, start);             // rest of own half, masked

        float dyo = fmaxf(fmaxf(__fsub_rn(scymin[co], qy),
                                __fsub_rn(qy, scymax[co])), 0.0f);
        if (!(__fmul_rn(__fmul_rn(dyo, dyo), STOP) > __uint_as_float(thrBits)))
            scan_chunk(co, -1);
    }

    // right phase (group x-bounds monotone -> break safe)
    for (int g = g0 + 1; g < NGR; g++) {
        float rb = fmaxf(__fsub_rn(sgxmin[g], qx), 0.0f);
        float rb2 = __fmul_rn(rb, rb);
        if (__fmul_rn(rb2, STOP) > __uint_as_float(thrBits)) break;
        #pragma unroll
        for (int h = 0; h < 2; h++) {
            int c = 2 * g + h;
            float dy = fmaxf(fmaxf(__fsub_rn(scymin[c], qy),
                                   __fsub_rn(qy, scymax[c])), 0.0f);
            float bound = __fadd_rn(rb2, __fmul_rn(dy, dy));
            if (!(__fmul_rn(bound, STOP) > __uint_as_float(thrBits)))
                scan_chunk(c, -1);
        }
    }
    // left phase
    for (int g = g0 - 1; g >= 0; g--) {
        float lb = fmaxf(__fsub_rn(qx, sgxmax[g]), 0.0f);
        float lb2 = __fmul_rn(lb, lb);
        if (__fmul_rn(lb2, STOP) > __uint_as_float(thrBits)) break;
        #pragma unroll
        for (int h = 0; h < 2; h++) {
            int c = 2 * g + h;
            float dy = fmaxf(fmaxf(__fsub_rn(scymin[c], qy),
                                   __fsub_rn(qy, scymax[c])), 0.0f);
            float bound = __fadd_rn(lb2, __fmul_rn(dy, dy));
            if (!(__fmul_rn(bound, STOP) > __uint_as_float(thrBits)))
                scan_chunk(c, -1);
        }
    }

    if (cnt > 0) {       // final flush
        __syncwarp(FULLMASK);
        unsigned long long v = (lane < cnt) ? buf[lane] : ~0ULL;
        warp_sort32(v, lane);
        warp_merge(best, v, lane);
    }

    g_knn_idx[((size_t)b * NQUERY + q) * NS + lane] =
        (int)(unsigned)(best & 0xffffffffu);
}

// -------------------------------------------------------------- gather ----
constexpr int OUT_CH = 3 + NCH;                // 67
constexpr int ELEMS  = NQUERY * NS;            // 65536 per (b, ch)
constexpr int NV     = ELEMS / 4;              // 16384 float4 per (b, ch)
constexpr int NGRP   = 17;
constexpr int GSPLIT = 2;
constexpr int GATHER_THREADS = 1024;
constexpr int GATHER_SMEM = (NPTS + NQUERY) * 16;   // 160 KB

__global__ __launch_bounds__(GATHER_THREADS, 1)
void gather_kernel(const float* __restrict__ xyz,
                   const float* __restrict__ new_xyz,
                   const float* __restrict__ feats,
                   float* __restrict__ out) {
    extern __shared__ float4 s4[];
    float4* srow = s4;            // [NPTS]
    float4* sq   = s4 + NPTS;     // [NQUERY] (group 0 only)

    const int half = blockIdx.x % GSPLIT;
    const int bg   = blockIdx.x / GSPLIT;
    const int b    = bg / NGRP;
    const int g    = bg % NGRP;
    const int tid  = threadIdx.x;

    if (g > 0) {
        const int f0 = 4 * (g - 1);
        const float* c0 = feats + ((size_t)b * NCH + f0) * NPTS;
        const float* c1 = c0 + NPTS;
        const float* c2 = c1 + NPTS;
        const float* c3 = c2 + NPTS;
        for (int i = tid; i < NPTS; i += GATHER_THREADS)
            srow[i] = make_float4(__ldg(c0 + i), __ldg(c1 + i),
                                  __ldg(c2 + i), __ldg(c3 + i));
    } else {
        const float* src = xyz + (size_t)b * NPTS * 3;
        for (int i = tid; i < NPTS; i += GATHER_THREADS)
            srow[i] = make_float4(src[3 * i], src[3 * i + 1], src[3 * i + 2], 0.0f);
        const float* qs = new_xyz + (size_t)b * NQUERY * 3;
        for (int i = tid; i < NQUERY; i += GATHER_THREADS)
            sq[i] = make_float4(qs[3 * i], qs[3 * i + 1], qs[3 * i + 2], 0.0f);
    }
    __syncthreads();

    const int4* idx4 = reinterpret_cast<const int4*>(g_knn_idx + (size_t)b * ELEMS);
    constexpr int NVH = NV / GSPLIT;            // 8192 per block
    const int e0 = half * NVH;

    if (g > 0) {
        const int ch0 = 3 + 4 * (g - 1);
        float4* o = reinterpret_cast<float4*>(out + ((size_t)b * OUT_CH + ch0) * ELEMS);
        #pragma unroll
        for (int it = 0; it < NVH / GATHER_THREADS; it++) {
            int e = e0 + it * GATHER_THREADS + tid;
            int4 n = idx4[e];
            float4 p0 = srow[n.x], p1 = srow[n.y], p2 = srow[n.z], p3 = srow[n.w];
            o[e]          = make_float4(p0.x, p1.x, p2.x, p3.x);
            o[e + NV]     = make_float4(p0.y, p1.y, p2.y, p3.y);
            o[e + 2 * NV] = make_float4(p0.z, p1.z, p2.z, p3.z);
            o[e + 3 * NV] = make_float4(p0.w, p1.w, p2.w, p3.w);
        }
    } else {
        float4* o = reinterpret_cast<float4*>(out + (size_t)b * OUT_CH * ELEMS);
        #pragma unroll
        for (int it = 0; it < NVH / GATHER_THREADS; it++) {
            int e = e0 + it * GATHER_THREADS + tid;
            int4 n = idx4[e];
            float4 p0 = srow[n.x], p1 = srow[n.y], p2 = srow[n.z], p3 = srow[n.w];
            float4 qv = sq[e >> 3];             // query = (4e)/32
            o[e]          = make_float4(__fsub_rn(p0.x, qv.x), __fsub_rn(p1.x, qv.x),
                                        __fsub_rn(p2.x, qv.x), __fsub_rn(p3.x, qv.x));
            o[e + NV]     = make_float4(__fsub_rn(p0.y, qv.y), __fsub_rn(p1.y, qv.y),
                                        __fsub_rn(p2.y, qv.y), __fsub_rn(p3.y, qv.y));
            o[e + 2 * NV] = make_float4(__fsub_rn(p0.z, qv.z), __fsub_rn(p1.z, qv.z),
                                        __fsub_rn(p2.z, qv.z), __fsub_rn(p3.z, qv.z));
        }
    }
}

// -------------------------------------------------------------- launch ----
extern "C" void kernel_launch(void* const* d_in, const int* in_sizes, int n_in,
                              void* d_out, int out_size) {
    const float* xyz      = (const float*)d_in[0];   // (4, 8192, 3) f32
    const float* new_xyz  = (const float*)d_in[1];   // (4, 2048, 3) f32
    // d_in[2], d_in[3]: components (int64) -- dead (LAMBDA = 0.5)
    const float* feats    = (const float*)d_in[4];   // (4, 64, 8192) f32
    float* out = (float*)d_out;                      // (4, 67, 2048, 32) f32

    cudaFuncSetAttribute(gather_kernel,
                         cudaFuncAttributeMaxDynamicSharedMemorySize, GATHER_SMEM);

    hist_kernel<<<BATCH * PARTS, 256>>>(xyz);
    scan_kernel<<<BATCH, 256>>>();
    scatter_kernel<<<BATCH * PARTS, 256>>>(xyz);
    ysort_kernel<<<BATCH * NGR, 256>>>();
    knn_kernel<<<BATCH * (NQUERY / QPB), KNN_THREADS>>>(new_xyz);
    gather_kernel<<<BATCH * NGRP * GSPLIT, GATHER_THREADS, GATHER_SMEM>>>(
        xyz, new_xyz, feats, out);
}

// round 16
// speedup vs baseline: 1.2254x; 1.0072x over previous
#include <cuda_runtime.h>
#include <cstdint>

// GAGKNNQueryAndGroup on GB300.
// LAMBDA = 0.5 -> lam == 1-lam: rescale scales every distance by 0.5 uniformly,
// ordering is plain squared-distance KNN; components inputs dead.
//
// R16 = R15 (kernels byte-identical) + knn/gather OVERLAP:
//  - gather is launched with programmatic dependent launch (PDL); knn blocks
//    call cudaTriggerProgrammaticLaunchCompletion() at entry, so gather blocks
//    become resident during knn. Resource fit: knn ~3.5 x 128-thr blocks/SM
//    (22KB smem) + one 1024-thr/160KB gather block co-reside; knn never waits
//    on gather -> no deadlock.
//  - gather stages its smem rows (knn-independent), then spin-waits on a
//    per-batch done counter (knn blocks: threadfence + syncthreads + relaxed
//    atomicAdd; gather: volatile spin + threadfence) before reading indices.
//  - counters reset each launch in scan_kernel (replay-deterministic).
// Failure mode if PDL serializes under capture: spin passes immediately ->
// exactly R15 behavior. Exactness machinery unchanged (reference fp op order,
// order-invariant top-32 of unique 64-bit keys, conservative prunes).

#define FULLMASK 0xffffffffu

constexpr int BATCH  = 4;
constexpr int NPTS   = 8192;
constexpr int NQUERY = 2048;
constexpr int NCH    = 64;
constexpr int NS     = 32;
constexpr int NBINS  = 256;
constexpr int NGR    = 32;                // 256-pt x-groups per batch
constexpr int NCHK   = 64;                // 128-pt y-half chunks per batch
constexpr int PARTS  = 8;
constexpr int PPTS   = NPTS / PARTS;      // 1024
constexpr int QPB    = 4;                 // queries (warps) per knn block
constexpr int KNN_THREADS = QPB * 32;     // 128
constexpr int KNN_BLOCKS_PER_BATCH = NQUERY / QPB;   // 512
constexpr int BUFSZ  = 176;               // per-warp candidate buffer entries
constexpr float STOP = 0.9999f;

__device__ float g_bx[BATCH * NPTS];
__device__ float g_by[BATCH * NPTS];
__device__ float g_bz[BATCH * NPTS];
__device__ __align__(16) unsigned short g_bidx[BATCH * NPTS];
__device__ unsigned g_hist_part[BATCH * PARTS * NBINS];
__device__ unsigned g_partoff[BATCH * PARTS * NBINS];
__device__ int g_binstart[BATCH * NBINS];
__device__ float g_gxmin[BATCH * NGR];
__device__ float g_gxmax[BATCH * NGR];
__device__ float g_cymin[BATCH * NCHK];
__device__ float g_cymax[BATCH * NCHK];
__device__ int g_knn_idx[BATCH * NQUERY * NS];
__device__ unsigned g_done[BATCH];        // knn blocks completed per batch

__device__ __forceinline__ int binof(float x) {
    int b = (int)((x + 4.5f) * (NBINS / 9.0f));
    return min(max(b, 0), NBINS - 1);
}

// ---------------------------------------------------------------- prep ----
__global__ void hist_kernel(const float* __restrict__ xyz) {
    __shared__ unsigned h[NBINS];
    const int b = blockIdx.x / PARTS, p = blockIdx.x % PARTS;
    const int tid = threadIdx.x;
    for (int i = tid; i < NBINS; i += 256) h[i] = 0;
    __syncthreads();
    const int base = p * PPTS;
    for (int i = tid; i < PPTS; i += 256) {
        float x = xyz[((size_t)b * NPTS + base + i) * 3];
        atomicAdd(&h[binof(x)], 1u);
    }
    __syncthreads();
    for (int i = tid; i < NBINS; i += 256)
        g_hist_part[((size_t)b * PARTS + p) * NBINS + i] = h[i];
}

__global__ void scan_kernel() {
    __shared__ unsigned wsum[8];
    __shared__ int sstart[NBINS];
    const int b = blockIdx.x;
    const int tid = threadIdx.x;          // == bin, 256 threads
    const int lane = tid & 31, wid = tid >> 5;

    if (tid == 0) g_done[b] = 0;          // reset knn->gather flag

    unsigned v = 0;
    #pragma unroll
    for (int p = 0; p < PARTS; p++)
        v += g_hist_part[((size_t)b * PARTS + p) * NBINS + tid];

    unsigned incl = v;
    #pragma unroll
    for (int off = 1; off < 32; off <<= 1) {
        unsigned t = __shfl_up_sync(FULLMASK, incl, off);
        if (lane >= off) incl += t;
    }
    if (lane == 31) wsum[wid] = incl;
    __syncthreads();
    if (wid == 0) {
        unsigned s = (lane < 8) ? wsum[lane] : 0, o = s;
        #pragma unroll
        for (int off = 1; off < 8; off <<= 1) {
            unsigned t = __shfl_up_sync(FULLMASK, s, off);
            if (lane >= off) s += t;
        }
        if (lane < 8) wsum[lane] = s - o;
    }
    __syncthreads();
    unsigned excl = incl - v + wsum[wid];
    sstart[tid] = (int)excl;
    g_binstart[b * NBINS + tid] = (int)excl;

    unsigned run = excl;
    #pragma unroll
    for (int p = 0; p < PARTS; p++) {
        g_partoff[((size_t)b * PARTS + p) * NBINS + tid] = run;
        run += g_hist_part[((size_t)b * PARTS + p) * NBINS + tid];
    }
    __syncthreads();

    if (tid < NGR) {                      // conservative, MONOTONE group x-bounds
        int posL = tid * 256, posR = posL + 255;
        int lo = 0, hi = NBINS - 1;
        while (lo < hi) { int m = (lo + hi + 1) >> 1;
                          if (sstart[m] <= posL) lo = m; else hi = m - 1; }
        int binL = lo;
        lo = binL; hi = NBINS - 1;
        while (lo < hi) { int m = (lo + hi + 1) >> 1;
                          if (sstart[m] <= posR) lo = m; else hi = m - 1; }
        int binR = lo;
        float eL = (binL == 0) ? -1e30f
                 : binL * (9.0f / NBINS) - 4.5f - 1e-3f;
        float eR = (binR == NBINS - 1) ? 1e30f
                 : (binR + 1) * (9.0f / NBINS) - 4.5f + 1e-3f;
        g_gxmin[b * NGR + tid] = eL;
        g_gxmax[b * NGR + tid] = eR;
    }
}

__global__ void scatter_kernel(const float* __restrict__ xyz) {
    __shared__ unsigned cur[NBINS];
    const int b = blockIdx.x / PARTS, p = blockIdx.x % PARTS;
    const int tid = threadIdx.x;
    for (int i = tid; i < NBINS; i += 256)
        cur[i] = g_partoff[((size_t)b * PARTS + p) * NBINS + i];
    __syncthreads();
    const int base = p * PPTS;
    for (int i = tid; i < PPTS; i += 256) {
        const float* pt = xyz + ((size_t)b * NPTS + base + i) * 3;
        float x = pt[0], y = pt[1], z = pt[2];
        int pos = (int)atomicAdd(&cur[binof(x)], 1u);
        size_t o = (size_t)b * NPTS + pos;
        g_bx[o] = x; g_by[o] = y; g_bz[o] = z;
        g_bidx[o] = (unsigned short)(base + i);
    }
}

// Sort each 256-pt x-group by y (hybrid bitonic: j<32 via shfl, else smem);
// emit exact per-half y bounds.
__global__ void ysort_kernel() {
    __shared__ float sx[256], sy[256], sz[256];
    __shared__ unsigned short si[256];
    __shared__ unsigned long long sk[256];
    const int b = blockIdx.x / NGR, g = blockIdx.x % NGR;
    const int tid = threadIdx.x;
    const size_t base = (size_t)b * NPTS + g * 256;

    float y = g_by[base + tid];
    sx[tid] = g_bx[base + tid];
    sy[tid] = y;
    sz[tid] = g_bz[base + tid];
    si[tid] = g_bidx[base + tid];
    unsigned e = __float_as_uint(y);
    e = (e & 0x80000000u) ? ~e : (e | 0x80000000u);   // order-preserving
    unsigned long long v = ((unsigned long long)e << 32) | (unsigned)tid;

    auto shfl_stage = [&](int k, int j) {
        unsigned long long o = __shfl_xor_sync(FULLMASK, v, j);
        bool keepMin = (((tid & k) == 0) == ((tid & j) == 0));
        bool less = v < o;                 // keys unique -> consistent
        v = (less == keepMin) ? v : o;
    };
    auto smem_stage = [&](int k, int j) {
        sk[tid] = v;
        __syncthreads();
        unsigned long long o = sk[tid ^ j];
        bool keepMin = (((tid & k) == 0) == ((tid & j) == 0));
        bool less = v < o;
        v = (less == keepMin) ? v : o;
        __syncthreads();
    };

    #pragma unroll
    for (int k = 2; k <= 32; k <<= 1)
        for (int j = k >> 1; j > 0; j >>= 1) shfl_stage(k, j);
    smem_stage(64, 32);
    #pragma unroll
    for (int j = 16; j > 0; j >>= 1) shfl_stage(64, j);
    smem_stage(128, 64); smem_stage(128, 32);
    #pragma unroll
    for (int j = 16; j > 0; j >>= 1) shfl_stage(128, j);
    smem_stage(256, 128); smem_stage(256, 64); smem_stage(256, 32);
    #pragma unroll
    for (int j = 16; j > 0; j >>= 1) shfl_stage(256, j);

    int src = (int)(v & 0xffu);
    float yv = sy[src];
    g_bx[base + tid] = sx[src];
    g_by[base + tid] = yv;
    g_bz[base + tid] = sz[src];
    g_bidx[base + tid] = si[src];
    if (tid == 0)   g_cymin[b * NCHK + 2 * g]     = yv;
    if (tid == 127) g_cymax[b * NCHK + 2 * g]     = yv;
    if (tid == 128) g_cymin[b * NCHK + 2 * g + 1] = yv;
    if (tid == 255) g_cymax[b * NCHK + 2 * g + 1] = yv;
}

// ------------------------------------------------------------ knn utils ----
__device__ __forceinline__ float sqdist(float qx, float qy, float qz,
                                        float x, float y, float z) {
    // No FMA contraction: matches reference (diff*diff then sum) bit-exactly.
    float dx = qx - x, dy = qy - y, dz = qz - z;
    return __fadd_rn(__fadd_rn(__fmul_rn(dx, dx), __fmul_rn(dy, dy)),
                     __fmul_rn(dz, dz));
}

__device__ __forceinline__ void warp_sort32(unsigned long long& v, int lane) {
    #pragma unroll
    for (int k = 2; k <= 32; k <<= 1) {
        #pragma unroll
        for (int j = k >> 1; j > 0; j >>= 1) {
            unsigned long long o = __shfl_xor_sync(FULLMASK, v, j);
            bool keepMin = (((lane & k) == 0) == ((lane & j) == 0));
            bool less = v < o;
            v = (less == keepMin) ? v : o;
        }
    }
}

__device__ __forceinline__ void warp_merge(unsigned long long& best,
                                           unsigned long long p, int lane) {
    unsigned long long bo = __shfl_sync(FULLMASK, p, 31 - lane);
    unsigned long long v = (best < bo) ? best : bo;
    #pragma unroll
    for (int j = 16; j > 0; j >>= 1) {
        unsigned long long o = __shfl_xor_sync(FULLMASK, v, j);
        bool lower = (lane & j) == 0;
        bool less = v < o;
        v = (less == lower) ? v : o;
    }
    best = v;
}

// ----------------------------------------------------------------- knn ----
__global__ __launch_bounds__(KNN_THREADS, 12)
void knn_kernel(const float* __restrict__ new_xyz) {
    __shared__ float sgxmin[NGR], sgxmax[NGR], scymin[NCHK], scymax[NCHK];
    __shared__ unsigned long long sbuf[QPB][BUFSZ];

    const int blocks_per_batch = KNN_BLOCKS_PER_BATCH;   // 512
    const int b    = blockIdx.x / blocks_per_batch;
    const int qblk = blockIdx.x % blocks_per_batch;

    if (threadIdx.x < NCHK) {
        scymin[threadIdx.x] = g_cymin[b * NCHK + threadIdx.x];
        scymax[threadIdx.x] = g_cymax[b * NCHK + threadIdx.x];
        if (threadIdx.x < NGR) {
            sgxmin[threadIdx.x] = g_gxmin[b * NGR + threadIdx.x];
            sgxmax[threadIdx.x] = g_gxmax[b * NGR + threadIdx.x];
        }
    }
    __syncthreads();

    // Let the dependent gather launch start staging while we compute.
    cudaTriggerProgrammaticLaunchCompletion();

    const int w    = threadIdx.x >> 5;
    const int lane = threadIdx.x & 31;
    const int q    = qblk * QPB + w;
    unsigned long long* buf = sbuf[w];

    const float* bxp = g_bx + (size_t)b * NPTS;
    const float* byp = g_by + (size_t)b * NPTS;
    const float* bzp = g_bz + (size_t)b * NPTS;
    const unsigned short* bip = g_bidx + (size_t)b * NPTS;
    const float4* px = (const float4*)bxp;
    const float4* py = (const float4*)byp;
    const float4* pz = (const float4*)bzp;
    const uint2*  pi = (const uint2*)bip;

    const float* nq = new_xyz + ((size_t)b * NQUERY + q) * 3;
    const float qx = __ldg(nq), qy = __ldg(nq + 1), qz = __ldg(nq + 2);

    unsigned long long best = ~0ULL;
    unsigned thrBits = 0xffffffffu;
    int cnt = 0;
    const unsigned lmask = (1u << lane) - 1u;

    // ---- append one chunk's candidates (optionally masking [ms, ms+32)) ----
    auto scan_chunk = [&](int c, int ms) {
        const int e0 = c * 32 + lane;
        float4 X = __ldg(px + e0);
        float4 Y = __ldg(py + e0);
        float4 Z = __ldg(pz + e0);

        unsigned u0 = __float_as_uint(sqdist(qx, qy, qz, X.x, Y.x, Z.x));
        unsigned u1 = __float_as_uint(sqdist(qx, qy, qz, X.y, Y.y, Z.y));
        unsigned u2 = __float_as_uint(sqdist(qx, qy, qz, X.z, Y.z, Z.z));
        unsigned u3 = __float_as_uint(sqdist(qx, qy, qz, X.w, Y.w, Z.w));

        if (ms >= 0) {                    // bootstrap-duplicate mask
            const int i0 = c * 128 + lane * 4;
            if ((unsigned)(i0 + 0 - ms) < 32u) u0 = 0xffffffffu;
            if ((unsigned)(i0 + 1 - ms) < 32u) u1 = 0xffffffffu;
            if ((unsigned)(i0 + 2 - ms) < 32u) u2 = 0xffffffffu;
            if ((unsigned)(i0 + 3 - ms) < 32u) u3 = 0xffffffffu;
        }

        unsigned mn = min(min(u0, u1), min(u2, u3));
        if (!__ballot_sync(FULLMASK, mn <= thrBits)) return;

        uint2 pk = __ldg(pi + e0);
        unsigned m0 = __ballot_sync(FULLMASK, u0 <= thrBits);
        if (m0) {
            if ((m0 >> lane) & 1u)
                buf[cnt + __popc(m0 & lmask)] =
                    ((unsigned long long)u0 << 32) | (pk.x & 0xffffu);
            cnt += __popc(m0);
        }
        unsigned m1 = __ballot_sync(FULLMASK, u1 <= thrBits);
        if (m1) {
            if ((m1 >> lane) & 1u)
                buf[cnt + __popc(m1 & lmask)] =
                    ((unsigned long long)u1 << 32) | (pk.x >> 16);
            cnt += __popc(m1);
        }
        unsigned m2 = __ballot_sync(FULLMASK, u2 <= thrBits);
        if (m2) {
            if ((m2 >> lane) & 1u)
                buf[cnt + __popc(m2 & lmask)] =
                    ((unsigned long long)u2 << 32) | (pk.y & 0xffffu);
            cnt += __popc(m2);
        }
        unsigned m3 = __ballot_sync(FULLMASK, u3 <= thrBits);
        if (m3) {
            if ((m3 >> lane) & 1u)
                buf[cnt + __popc(m3 & lmask)] =
                    ((unsigned long long)u3 << 32) | (pk.y >> 16);
            cnt += __popc(m3);
        }

        while (cnt >= 32) {               // drain (LIFO)
            __syncwarp(FULLMASK);
            unsigned long long v = buf[cnt - 32 + lane];
            cnt -= 32;
            warp_sort32(v, lane);
            warp_merge(best, v, lane);
            thrBits = (unsigned)(__shfl_sync(FULLMASK, best, 31) >> 32);
        }
    };

    const int pos0 = __ldg(&g_binstart[b * NBINS + binof(qx)]);
    const int g0 = min(pos0 >> 8, NGR - 1);

    // pick bootstrap half = the y-closer half of the query's own group
    const int ca = 2 * g0, cbh = 2 * g0 + 1;
    float dya = fmaxf(fmaxf(__fsub_rn(scymin[ca], qy),
                            __fsub_rn(qy, scymax[ca])), 0.0f);
    float dyb = fmaxf(fmaxf(__fsub_rn(scymin[cbh], qy),
                            __fsub_rn(qy, scymax[cbh])), 0.0f);
    const int cb = (dya <= dyb) ? ca : cbh;      // bootstrap half
    const int co = (dya <= dyb) ? cbh : ca;      // other half

    {   // bootstrap: ~32 contiguous y-near points of cb (warp-parallel probe)
        float yp = __ldg(byp + cb * 128 + lane * 4);
        unsigned below = __ballot_sync(FULLMASK, yp < qy);
        int lo = cb * 128 + __popc(below) * 4;   // ~first pos with y >= qy
        int start = min(max(lo - 16, cb * 128), cb * 128 + 96);
        int pt = start + lane;
        float X = __ldg(bxp + pt), Y = __ldg(byp + pt), Z = __ldg(bzp + pt);
        unsigned short id = __ldg(bip + pt);
        unsigned long long v =
            ((unsigned long long)__float_as_uint(sqdist(qx, qy, qz, X, Y, Z)) << 32)
            | (unsigned)id;
        warp_sort32(v, lane);
        best = v;                          // 32 sorted real keys
        thrBits = (unsigned)(__shfl_sync(FULLMASK, best, 31) >> 32);

        scan_chunk(cb, start);             // rest of own half, masked

        float dyo = fmaxf(fmaxf(__fsub_rn(scymin[co], qy),
                                __fsub_rn(qy, scymax[co])), 0.0f);
        if (!(__fmul_rn(__fmul_rn(dyo, dyo), STOP) > __uint_as_float(thrBits)))
            scan_chunk(co, -1);
    }

    // right phase (group x-bounds monotone -> break safe)
    for (int g = g0 + 1; g < NGR; g++) {
        float rb = fmaxf(__fsub_rn(sgxmin[g], qx), 0.0f);
        float rb2 = __fmul_rn(rb, rb);
        if (__fmul_rn(rb2, STOP) > __uint_as_float(thrBits)) break;
        #pragma unroll
        for (int h = 0; h < 2; h++) {
            int c = 2 * g + h;
            float dy = fmaxf(fmaxf(__fsub_rn(scymin[c], qy),
                                   __fsub_rn(qy, scymax[c])), 0.0f);
            float bound = __fadd_rn(rb2, __fmul_rn(dy, dy));
            if (!(__fmul_rn(bound, STOP) > __uint_as_float(thrBits)))
                scan_chunk(c, -1);
        }
    }
    // left phase
    for (int g = g0 - 1; g >= 0; g--) {
        float lb = fmaxf(__fsub_rn(qx, sgxmax[g]), 0.0f);
        float lb2 = __fmul_rn(lb, lb);
        if (__fmul_rn(lb2, STOP) > __uint_as_float(thrBits)) break;
        #pragma unroll
        for (int h = 0; h < 2; h++) {
            int c = 2 * g + h;
            float dy = fmaxf(fmaxf(__fsub_rn(scymin[c], qy),
                                   __fsub_rn(qy, scymax[c])), 0.0f);
            float bound = __fadd_rn(lb2, __fmul_rn(dy, dy));
            if (!(__fmul_rn(bound, STOP) > __uint_as_float(thrBits)))
                scan_chunk(c, -1);
        }
    }

    if (cnt > 0) {       // final flush
        __syncwarp(FULLMASK);
        unsigned long long v = (lane < cnt) ? buf[lane] : ~0ULL;
        warp_sort32(v, lane);
        warp_merge(best, v, lane);
    }

    g_knn_idx[((size_t)b * NQUERY + q) * NS + lane] =
        (int)(unsigned)(best & 0xffffffffu);

    // publish: all idx writes -> fence -> barrier -> one relaxed counter bump
    __threadfence();
    __syncthreads();
    if (threadIdx.x == 0) atomicAdd(&g_done[b], 1u);
}

// -------------------------------------------------------------- gather ----
constexpr int OUT_CH = 3 + NCH;                // 67
constexpr int ELEMS  = NQUERY * NS;            // 65536 per (b, ch)
constexpr int NV     = ELEMS / 4;              // 16384 float4 per (b, ch)
constexpr int NGRP   = 17;
constexpr int GSPLIT = 2;
constexpr int GATHER_THREADS = 1024;
constexpr int GATHER_SMEM = (NPTS + NQUERY) * 16;   // 160 KB

__global__ __launch_bounds__(GATHER_THREADS, 1)
void gather_kernel(const float* __restrict__ xyz,
                   const float* __restrict__ new_xyz,
                   const float* __restrict__ feats,
                   float* __restrict__ out) {
    extern __shared__ float4 s4[];
    float4* srow = s4;            // [NPTS]
    float4* sq   = s4 + NPTS;     // [NQUERY] (group 0 only)

    const int half = blockIdx.x % GSPLIT;
    const int bg   = blockIdx.x / GSPLIT;
    const int b    = bg / NGRP;
    const int g    = bg % NGRP;
    const int tid  = threadIdx.x;

    // ---- stage (independent of knn; overlaps with knn under PDL) ----
    if (g > 0) {
        const int f0 = 4 * (g - 1);
        const float* c0 = feats + ((size_t)b * NCH + f0) * NPTS;
        const float* c1 = c0 + NPTS;
        const float* c2 = c1 + NPTS;
        const float* c3 = c2 + NPTS;
        for (int i = tid; i < NPTS; i += GATHER_THREADS)
            srow[i] = make_float4(__ldg(c0 + i), __ldg(c1 + i),
                                  __ldg(c2 + i), __ldg(c3 + i));
    } else {
        const float* src = xyz + (size_t)b * NPTS * 3;
        for (int i = tid; i < NPTS; i += GATHER_THREADS)
            srow[i] = make_float4(src[3 * i], src[3 * i + 1], src[3 * i + 2], 0.0f);
        const float* qs = new_xyz + (size_t)b * NQUERY * 3;
        for (int i = tid; i < NQUERY; i += GATHER_THREADS)
            sq[i] = make_float4(qs[3 * i], qs[3 * i + 1], qs[3 * i + 2], 0.0f);
    }
    __syncthreads();

    // ---- wait for this batch's knn blocks ----
    if (tid == 0) {
        volatile unsigned* done = (volatile unsigned*)&g_done[b];
        while (*done < (unsigned)KNN_BLOCKS_PER_BATCH) __nanosleep(200);
    }
    __syncthreads();
    __threadfence();                       // acquire: idx writes now visible

    const int4* idx4 = reinterpret_cast<const int4*>(g_knn_idx + (size_t)b * ELEMS);
    constexpr int NVH = NV / GSPLIT;            // 8192 per block
    const int e0 = half * NVH;

    if (g > 0) {
        const int ch0 = 3 + 4 * (g - 1);
        float4* o = reinterpret_cast<float4*>(out + ((size_t)b * OUT_CH + ch0) * ELEMS);
        #pragma unroll
        for (int it = 0; it < NVH / GATHER_THREADS; it++) {
            int e = e0 + it * GATHER_THREADS + tid;
            int4 n = idx4[e];
            float4 p0 = srow[n.x], p1 = srow[n.y], p2 = srow[n.z], p3 = srow[n.w];
            o[e]          = make_float4(p0.x, p1.x, p2.x, p3.x);
            o[e + NV]     = make_float4(p0.y, p1.y, p2.y, p3.y);
            o[e + 2 * NV] = make_float4(p0.z, p1.z, p2.z, p3.z);
            o[e + 3 * NV] = make_float4(p0.w, p1.w, p2.w, p3.w);
        }
    } else {
        float4* o = reinterpret_cast<float4*>(out + (size_t)b * OUT_CH * ELEMS);
        #pragma unroll
        for (int it = 0; it < NVH / GATHER_THREADS; it++) {
            int e = e0 + it * GATHER_THREADS + tid;
            int4 n = idx4[e];
            float4 p0 = srow[n.x], p1 = srow[n.y], p2 = srow[n.z], p3 = srow[n.w];
            float4 qv = sq[e >> 3];             // query = (4e)/32
            o[e]          = make_float4(__fsub_rn(p0.x, qv.x), __fsub_rn(p1.x, qv.x),
                                        __fsub_rn(p2.x, qv.x), __fsub_rn(p3.x, qv.x));
            o[e + NV]     = make_float4(__fsub_rn(p0.y, qv.y), __fsub_rn(p1.y, qv.y),
                                        __fsub_rn(p2.y, qv.y), __fsub_rn(p3.y, qv.y));
            o[e + 2 * NV] = make_float4(__fsub_rn(p0.z, qv.z), __fsub_rn(p1.z, qv.z),
                                        __fsub_rn(p2.z, qv.z), __fsub_rn(p3.z, qv.z));
        }
    }
}

// -------------------------------------------------------------- launch ----
extern "C" void kernel_launch(void* const* d_in, const int* in_sizes, int n_in,
                              void* d_out, int out_size) {
    const float* xyz      = (const float*)d_in[0];   // (4, 8192, 3) f32
    const float* new_xyz  = (const float*)d_in[1];   // (4, 2048, 3) f32
    // d_in[2], d_in[3]: components (int64) -- dead (LAMBDA = 0.5)
    const float* feats    = (const float*)d_in[4];   // (4, 64, 8192) f32
    float* out = (float*)d_out;                      // (4, 67, 2048, 32) f32

    cudaFuncSetAttribute(gather_kernel,
                         cudaFuncAttributeMaxDynamicSharedMemorySize, GATHER_SMEM);

    hist_kernel<<<BATCH * PARTS, 256>>>(xyz);
    scan_kernel<<<BATCH, 256>>>();
    scatter_kernel<<<BATCH * PARTS, 256>>>(xyz);
    ysort_kernel<<<BATCH * NGR, 256>>>();
    knn_kernel<<<BATCH * KNN_BLOCKS_PER_BATCH, KNN_THREADS>>>(new_xyz);

    // gather: programmatic dependent launch -> starts (stages smem) while knn
    // is still running; per-batch done-flags gate the index-dependent part.
    {
        cudaLaunchConfig_t cfg = {};
        cfg.gridDim  = dim3(BATCH * NGRP * GSPLIT);
        cfg.blockDim = dim3(GATHER_THREADS);
        cfg.dynamicSmemBytes = GATHER_SMEM;
        cfg.stream = 0;
        cudaLaunchAttribute attr[1];
        attr[0].id = cudaLaunchAttributeProgrammaticStreamSerialization;
        attr[0].val.programmaticStreamSerializationAllowed = 1;
        cfg.attrs = attr;
        cfg.numAttrs = 1;
        cudaLaunchKernelEx(&cfg, gather_kernel, xyz, new_xyz, feats, out);
    }
}